// round 5
// baseline (speedup 1.0000x reference)
#include <cuda_runtime.h>
#include <cstddef>

#define S_LEN 1024
#define D_DIM 64
#define BH    64   // B*H = 4*16

// Scratch: MK[bh][u][d] = sum_t mask[bh][u][t] * K[bh][t][d]   (16 MB)
static __device__ float g_MK[(size_t)BH * S_LEN * D_DIM];

// ---------------------------------------------------------------------------
// GEMM NN: C[1024,64] = A[1024,1024] @ B[1024,64], batched over blockIdx.z.
// Used for K1 (A=mask, B=K, C=MK) and K3 (A=attn, B=V, C=context).
// Tile: BM=128, BN=64, BK=32. 256 threads, 8x4 micro-tile per thread.
// ---------------------------------------------------------------------------
__global__ __launch_bounds__(256) void gemm_nn_kernel(
    const float* __restrict__ A,
    const float* __restrict__ B,
    float* __restrict__ C)
{
    __shared__ float As[32][132];  // transposed: As[k][m], padded
    __shared__ float Bs[32][68];   // Bs[k][n], padded

    const int bh  = blockIdx.z;
    const int m0  = blockIdx.x * 128;
    const float* Ab = A + (size_t)bh * S_LEN * S_LEN;
    const float* Bb = B + (size_t)bh * S_LEN * D_DIM;
    float*       Cb = C + (size_t)bh * S_LEN * D_DIM;

    const int tid = threadIdx.x;
    const int rt  = tid >> 4;   // 0..15 -> rows rt*8..rt*8+7
    const int ct  = tid & 15;   // 0..15 -> cols ct*4..ct*4+3

    float acc[8][4];
#pragma unroll
    for (int i = 0; i < 8; i++)
#pragma unroll
        for (int j = 0; j < 4; j++) acc[i][j] = 0.0f;

    for (int k0 = 0; k0 < S_LEN; k0 += 32) {
        // Load A tile 128x32 (transposed into As)
#pragma unroll
        for (int p = 0; p < 4; p++) {
            int idx = p * 256 + tid;
            int r = idx >> 3;        // 0..127
            int c4 = idx & 7;        // 0..7
            float4 v = *(const float4*)&Ab[(size_t)(m0 + r) * S_LEN + k0 + c4 * 4];
            As[c4 * 4 + 0][r] = v.x;
            As[c4 * 4 + 1][r] = v.y;
            As[c4 * 4 + 2][r] = v.z;
            As[c4 * 4 + 3][r] = v.w;
        }
        // Load B tile 32x64
#pragma unroll
        for (int p = 0; p < 2; p++) {
            int idx = p * 256 + tid;
            int r = idx >> 4;        // 0..31
            int c4 = idx & 15;       // 0..15
            float4 v = *(const float4*)&Bb[(size_t)(k0 + r) * D_DIM + c4 * 4];
            *(float4*)&Bs[r][c4 * 4] = v;
        }
        __syncthreads();

#pragma unroll
        for (int k = 0; k < 32; k++) {
            float4 b = *(float4*)&Bs[k][ct * 4];
            float4 alo = *(float4*)&As[k][rt * 8];
            float4 ahi = *(float4*)&As[k][rt * 8 + 4];
            float a[8] = {alo.x, alo.y, alo.z, alo.w, ahi.x, ahi.y, ahi.z, ahi.w};
#pragma unroll
            for (int i = 0; i < 8; i++) {
                acc[i][0] = fmaf(a[i], b.x, acc[i][0]);
                acc[i][1] = fmaf(a[i], b.y, acc[i][1]);
                acc[i][2] = fmaf(a[i], b.z, acc[i][2]);
                acc[i][3] = fmaf(a[i], b.w, acc[i][3]);
            }
        }
        __syncthreads();
    }

#pragma unroll
    for (int i = 0; i < 8; i++) {
        float4 v = make_float4(acc[i][0], acc[i][1], acc[i][2], acc[i][3]);
        *(float4*)&Cb[(size_t)(m0 + rt * 8 + i) * D_DIM + ct * 4] = v;
    }
}

// ---------------------------------------------------------------------------
// K2: P = scale * Q @ MK^T, fused row softmax, write attn.
// Block: 32 rows x full 1024 cols. 512 threads.
// Thread (rg = t/64 in 0..7, cg = t%64) owns acc[i][m] = P[rg*4+i][m*64+cg].
// MK streamed in 4 chunks of 256 rows through shared memory.
// ---------------------------------------------------------------------------
#define K2_SMEM_FLOATS (32 * 68 + 256 * 68)
#define K2_SMEM_BYTES  (K2_SMEM_FLOATS * 4)

__global__ __launch_bounds__(512, 1) void scores_softmax_kernel(
    const float* __restrict__ Q,
    const float* __restrict__ MK,
    float* __restrict__ attn)
{
    extern __shared__ float sm[];
    float* Qs  = sm;               // [32][68]
    float* MKs = sm + 32 * 68;     // [256][68]
    float* red = MKs;              // aliased after compute phase
    __shared__ float rowstat[32];

    const int t    = threadIdx.x;
    const int bh   = blockIdx.y;
    const int row0 = blockIdx.x * 32;

    const float* Qb  = Q  + (size_t)bh * S_LEN * D_DIM;
    const float* MKb = MK + (size_t)bh * S_LEN * D_DIM;

    // Load Q tile 32x64, pre-scaled by 1/sqrt(64) = 0.125
    {
        int r  = t >> 4;    // 0..31
        int c4 = t & 15;    // 0..15
        float4 v = *(const float4*)&Qb[(size_t)(row0 + r) * D_DIM + c4 * 4];
        v.x *= 0.125f; v.y *= 0.125f; v.z *= 0.125f; v.w *= 0.125f;
        *(float4*)&Qs[r * 68 + c4 * 4] = v;
    }
    __syncthreads();

    const int rg = t >> 6;   // 0..7
    const int cg = t & 63;   // 0..63

    float acc[4][16];
#pragma unroll
    for (int i = 0; i < 4; i++)
#pragma unroll
        for (int m = 0; m < 16; m++) acc[i][m] = 0.0f;

#pragma unroll
    for (int nc = 0; nc < 4; nc++) {
        // Load MK chunk: rows [nc*256, nc*256+256), 64 cols
#pragma unroll
        for (int p = 0; p < 8; p++) {
            int idx = p * 512 + t;
            int r  = idx >> 4;    // 0..255
            int c4 = idx & 15;    // 0..15
            float4 v = *(const float4*)&MKb[(size_t)(nc * 256 + r) * D_DIM + c4 * 4];
            *(float4*)&MKs[r * 68 + c4 * 4] = v;
        }
        __syncthreads();

#pragma unroll
        for (int d4 = 0; d4 < 16; d4++) {
            float4 q[4], mv[4];
#pragma unroll
            for (int i = 0; i < 4; i++)
                q[i] = *(float4*)&Qs[(rg * 4 + i) * 68 + d4 * 4];
#pragma unroll
            for (int mm = 0; mm < 4; mm++)
                mv[mm] = *(float4*)&MKs[(mm * 64 + cg) * 68 + d4 * 4];
#pragma unroll
            for (int i = 0; i < 4; i++) {
#pragma unroll
                for (int mm = 0; mm < 4; mm++) {
                    float v = acc[i][nc * 4 + mm];
                    v = fmaf(q[i].x, mv[mm].x, v);
                    v = fmaf(q[i].y, mv[mm].y, v);
                    v = fmaf(q[i].z, mv[mm].z, v);
                    v = fmaf(q[i].w, mv[mm].w, v);
                    acc[i][nc * 4 + mm] = v;
                }
            }
        }
        __syncthreads();
    }

    // ---- fused softmax over each 1024-wide row ----
    // 1) per-thread max -> red[row][cg]
#pragma unroll
    for (int i = 0; i < 4; i++) {
        float lm = -1e30f;
#pragma unroll
        for (int m = 0; m < 16; m++) lm = fmaxf(lm, acc[i][m]);
        red[(rg * 4 + i) * 64 + cg] = lm;
    }
    __syncthreads();
    if (t < 32) {
        float mx = -1e30f;
#pragma unroll 8
        for (int c = 0; c < 64; c++) mx = fmaxf(mx, red[t * 64 + c]);
        rowstat[t] = mx;
    }
    __syncthreads();
    // 2) exp + per-thread sum -> red[row][cg]
#pragma unroll
    for (int i = 0; i < 4; i++) {
        float mx = rowstat[rg * 4 + i];
        float ls = 0.0f;
#pragma unroll
        for (int m = 0; m < 16; m++) {
            float e = __expf(acc[i][m] - mx);
            acc[i][m] = e;
            ls += e;
        }
        red[(rg * 4 + i) * 64 + cg] = ls;
    }
    __syncthreads();
    if (t < 32) {
        float sv = 0.0f;
#pragma unroll 8
        for (int c = 0; c < 64; c++) sv += red[t * 64 + c];
        rowstat[t] = 1.0f / sv;
    }
    __syncthreads();

    // 3) normalized write-out (coalesced: lanes vary cg)
    float* attnb = attn + ((size_t)bh * S_LEN + row0) * S_LEN;
#pragma unroll
    for (int i = 0; i < 4; i++) {
        float inv = rowstat[rg * 4 + i];
        size_t rbase = (size_t)(rg * 4 + i) * S_LEN;
#pragma unroll
        for (int m = 0; m < 16; m++) {
            attnb[rbase + m * 64 + cg] = acc[i][m] * inv;
        }
    }
}

// ---------------------------------------------------------------------------
extern "C" void kernel_launch(void* const* d_in, const int* in_sizes, int n_in,
                              void* d_out, int out_size)
{
    const float* Q    = (const float*)d_in[0];
    const float* Kt   = (const float*)d_in[1];
    const float* V    = (const float*)d_in[2];
    const float* mask = (const float*)d_in[3];

    float* ctx  = (float*)d_out;                                  // [BH,1024,64]
    float* attn = ctx + (size_t)BH * S_LEN * D_DIM;               // [BH,1024,1024]

    void* mkptr = nullptr;
    cudaGetSymbolAddress(&mkptr, g_MK);
    float* MK = (float*)mkptr;

    cudaFuncSetAttribute(scores_softmax_kernel,
                         cudaFuncAttributeMaxDynamicSharedMemorySize,
                         K2_SMEM_BYTES);

    // K1: MK = mask @ K
    gemm_nn_kernel<<<dim3(8, 1, BH), 256>>>(mask, Kt, MK);
    // K2: attn = softmax(scale * Q @ MK^T)
    scores_softmax_kernel<<<dim3(32, BH), 512, K2_SMEM_BYTES>>>(Q, MK, attn);
    // K3: ctx = attn @ V
    gemm_nn_kernel<<<dim3(8, 1, BH), 256>>>(attn, V, ctx);
}

// round 8
// speedup vs baseline: 1.0802x; 1.0802x over previous
#include <cuda_runtime.h>
#include <cstdint>
#include <cstddef>

#define S_LEN 1024
#define D_DIM 64
#define BH    64   // B*H = 4*16

// Scratch: MK[bh][u][d] = sum_t mask[bh][u][t] * K[bh][t][d]   (16 MB)
static __device__ float g_MK[(size_t)BH * S_LEN * D_DIM];

// ---------------------------------------------------------------------------
// tf32 helpers
// ---------------------------------------------------------------------------
__device__ __forceinline__ uint32_t f2tf32(float f) {
    uint32_t u;
    asm("cvt.rna.tf32.f32 %0, %1;" : "=r"(u) : "f"(f));
    return u;
}

#define MMA_TF32(d, a, b) \
    asm volatile( \
        "mma.sync.aligned.m16n8k8.row.col.f32.tf32.tf32.f32 " \
        "{%0,%1,%2,%3}, {%4,%5,%6,%7}, {%8,%9}, {%0,%1,%2,%3};" \
        : "+f"((d)[0]), "+f"((d)[1]), "+f"((d)[2]), "+f"((d)[3]) \
        : "r"((a)[0]), "r"((a)[1]), "r"((a)[2]), "r"((a)[3]), \
          "r"((b)[0]), "r"((b)[1]))

// ---------------------------------------------------------------------------
// Tensor-core (mma.sync tf32, 2-limb split) batched GEMM NN:
//   C[1024,64] = A[1024,1024] @ B[1024,64]     batch = blockIdx.y
// Tile: BM=128, BN=64, BK=16. 256 threads = 8 warps as 4(M) x 2(N),
// each warp 32x32 via m16n8k8 (2 m-tiles x 4 n-tiles), 3 limb products.
// ---------------------------------------------------------------------------
#define A_PITCH 20   // floats; frag loads conflict-free
#define B_PITCH 72   // floats; frag loads conflict-free

__global__ __launch_bounds__(256) void gemm_tc_kernel(
    const float* __restrict__ A,
    const float* __restrict__ B,
    float* __restrict__ C)
{
    __shared__ float As[2][128][A_PITCH];   // [limb][m][k]
    __shared__ float Bs[2][16][B_PITCH];    // [limb][k][n]

    const int t    = threadIdx.x;
    const int wid  = t >> 5;
    const int lane = t & 31;
    const int wm   = wid & 3;      // warp row  (0..3)
    const int wn   = wid >> 2;     // warp col  (0..1)
    const int g    = lane >> 2;    // group id  (0..7)
    const int c    = lane & 3;     // in-group  (0..3)

    const int bh = blockIdx.y;
    const int m0 = blockIdx.x * 128;

    const float* Ab = A + (size_t)bh * S_LEN * S_LEN;
    const float* Bb = B + (size_t)bh * S_LEN * D_DIM;
    float*       Cb = C + (size_t)bh * S_LEN * D_DIM;

    float acc[2][4][4];
#pragma unroll
    for (int i = 0; i < 2; i++)
#pragma unroll
        for (int j = 0; j < 4; j++)
#pragma unroll
            for (int q = 0; q < 4; q++) acc[i][j][q] = 0.0f;

    for (int k0 = 0; k0 < S_LEN; k0 += 16) {
        // ---- load A tile 128x16, split into tf32 hi/lo limbs ----
#pragma unroll
        for (int p = 0; p < 2; p++) {
            int idx = p * 256 + t;
            int r   = idx >> 2;          // 0..127
            int c4  = idx & 3;           // 0..3
            float4 v = *(const float4*)&Ab[(size_t)(m0 + r) * S_LEN + k0 + c4 * 4];
            float f[4] = {v.x, v.y, v.z, v.w};
            float4 hi, lo;
            float* hp = &hi.x; float* lp = &lo.x;
#pragma unroll
            for (int j = 0; j < 4; j++) {
                float h = __uint_as_float(f2tf32(f[j]));
                float l = __uint_as_float(f2tf32(f[j] - h));
                hp[j] = h; lp[j] = l;
            }
            *(float4*)&As[0][r][c4 * 4] = hi;
            *(float4*)&As[1][r][c4 * 4] = lo;
        }
        // ---- load B tile 16x64, split ----
        {
            int r  = t >> 4;             // 0..15
            int c4 = t & 15;             // 0..15
            float4 v = *(const float4*)&Bb[(size_t)(k0 + r) * D_DIM + c4 * 4];
            float f[4] = {v.x, v.y, v.z, v.w};
            float4 hi, lo;
            float* hp = &hi.x; float* lp = &lo.x;
#pragma unroll
            for (int j = 0; j < 4; j++) {
                float h = __uint_as_float(f2tf32(f[j]));
                float l = __uint_as_float(f2tf32(f[j] - h));
                hp[j] = h; lp[j] = l;
            }
            *(float4*)&Bs[0][r][c4 * 4] = hi;
            *(float4*)&Bs[1][r][c4 * 4] = lo;
        }
        __syncthreads();

#pragma unroll
        for (int ks = 0; ks < 2; ks++) {
            uint32_t a[2][2][4];   // [limb][mtile][reg]
            uint32_t b[2][4][2];   // [limb][ntile][reg]
#pragma unroll
            for (int l = 0; l < 2; l++)
#pragma unroll
                for (int mt = 0; mt < 2; mt++) {
                    int m = wm * 32 + mt * 16;
                    int k = ks * 8;
                    a[l][mt][0] = __float_as_uint(As[l][m + g][k + c]);
                    a[l][mt][1] = __float_as_uint(As[l][m + g + 8][k + c]);
                    a[l][mt][2] = __float_as_uint(As[l][m + g][k + c + 4]);
                    a[l][mt][3] = __float_as_uint(As[l][m + g + 8][k + c + 4]);
                }
#pragma unroll
            for (int l = 0; l < 2; l++)
#pragma unroll
                for (int nt = 0; nt < 4; nt++) {
                    int n = wn * 32 + nt * 8 + g;
                    int k = ks * 8;
                    b[l][nt][0] = __float_as_uint(Bs[l][k + c][n]);
                    b[l][nt][1] = __float_as_uint(Bs[l][k + c + 4][n]);
                }
#pragma unroll
            for (int mt = 0; mt < 2; mt++)
#pragma unroll
                for (int nt = 0; nt < 4; nt++) {
                    MMA_TF32(acc[mt][nt], a[0][mt], b[0][nt]);   // hh
                    MMA_TF32(acc[mt][nt], a[0][mt], b[1][nt]);   // h*lo
                    MMA_TF32(acc[mt][nt], a[1][mt], b[0][nt]);   // lo*h
                }
        }
        __syncthreads();
    }

    // ---- epilogue ----
#pragma unroll
    for (int mt = 0; mt < 2; mt++)
#pragma unroll
        for (int nt = 0; nt < 4; nt++) {
            int row = m0 + wm * 32 + mt * 16 + g;
            int col = wn * 32 + nt * 8 + 2 * c;
            float2 v0 = make_float2(acc[mt][nt][0], acc[mt][nt][1]);
            float2 v1 = make_float2(acc[mt][nt][2], acc[mt][nt][3]);
            *(float2*)&Cb[(size_t)row * D_DIM + col]       = v0;
            *(float2*)&Cb[(size_t)(row + 8) * D_DIM + col] = v1;
        }
}

// ---------------------------------------------------------------------------
// K2: P = scale * Q @ MK^T, fused row softmax, write attn.  (fp32, unchanged)
// ---------------------------------------------------------------------------
#define K2_SMEM_FLOATS (32 * 68 + 256 * 68)
#define K2_SMEM_BYTES  (K2_SMEM_FLOATS * 4)

__global__ __launch_bounds__(512, 1) void scores_softmax_kernel(
    const float* __restrict__ Q,
    const float* __restrict__ MK,
    float* __restrict__ attn)
{
    extern __shared__ float sm[];
    float* Qs  = sm;               // [32][68]
    float* MKs = sm + 32 * 68;     // [256][68]
    float* red = MKs;              // aliased after compute phase
    __shared__ float rowstat[32];

    const int t    = threadIdx.x;
    const int bh   = blockIdx.y;
    const int row0 = blockIdx.x * 32;

    const float* Qb  = Q  + (size_t)bh * S_LEN * D_DIM;
    const float* MKb = MK + (size_t)bh * S_LEN * D_DIM;

    {
        int r  = t >> 4;
        int c4 = t & 15;
        float4 v = *(const float4*)&Qb[(size_t)(row0 + r) * D_DIM + c4 * 4];
        v.x *= 0.125f; v.y *= 0.125f; v.z *= 0.125f; v.w *= 0.125f;
        *(float4*)&Qs[r * 68 + c4 * 4] = v;
    }
    __syncthreads();

    const int rg = t >> 6;
    const int cg = t & 63;

    float acc[4][16];
#pragma unroll
    for (int i = 0; i < 4; i++)
#pragma unroll
        for (int m = 0; m < 16; m++) acc[i][m] = 0.0f;

#pragma unroll
    for (int nc = 0; nc < 4; nc++) {
#pragma unroll
        for (int p = 0; p < 8; p++) {
            int idx = p * 512 + t;
            int r  = idx >> 4;
            int c4 = idx & 15;
            float4 v = *(const float4*)&MKb[(size_t)(nc * 256 + r) * D_DIM + c4 * 4];
            *(float4*)&MKs[r * 68 + c4 * 4] = v;
        }
        __syncthreads();

#pragma unroll
        for (int d4 = 0; d4 < 16; d4++) {
            float4 q[4], mv[4];
#pragma unroll
            for (int i = 0; i < 4; i++)
                q[i] = *(float4*)&Qs[(rg * 4 + i) * 68 + d4 * 4];
#pragma unroll
            for (int mm = 0; mm < 4; mm++)
                mv[mm] = *(float4*)&MKs[(mm * 64 + cg) * 68 + d4 * 4];
#pragma unroll
            for (int i = 0; i < 4; i++) {
#pragma unroll
                for (int mm = 0; mm < 4; mm++) {
                    float v = acc[i][nc * 4 + mm];
                    v = fmaf(q[i].x, mv[mm].x, v);
                    v = fmaf(q[i].y, mv[mm].y, v);
                    v = fmaf(q[i].z, mv[mm].z, v);
                    v = fmaf(q[i].w, mv[mm].w, v);
                    acc[i][nc * 4 + mm] = v;
                }
            }
        }
        __syncthreads();
    }

#pragma unroll
    for (int i = 0; i < 4; i++) {
        float lm = -1e30f;
#pragma unroll
        for (int m = 0; m < 16; m++) lm = fmaxf(lm, acc[i][m]);
        red[(rg * 4 + i) * 64 + cg] = lm;
    }
    __syncthreads();
    if (t < 32) {
        float mx = -1e30f;
#pragma unroll 8
        for (int c = 0; c < 64; c++) mx = fmaxf(mx, red[t * 64 + c]);
        rowstat[t] = mx;
    }
    __syncthreads();
#pragma unroll
    for (int i = 0; i < 4; i++) {
        float mx = rowstat[rg * 4 + i];
        float ls = 0.0f;
#pragma unroll
        for (int m = 0; m < 16; m++) {
            float e = __expf(acc[i][m] - mx);
            acc[i][m] = e;
            ls += e;
        }
        red[(rg * 4 + i) * 64 + cg] = ls;
    }
    __syncthreads();
    if (t < 32) {
        float sv = 0.0f;
#pragma unroll 8
        for (int c = 0; c < 64; c++) sv += red[t * 64 + c];
        rowstat[t] = 1.0f / sv;
    }
    __syncthreads();

    float* attnb = attn + ((size_t)bh * S_LEN + row0) * S_LEN;
#pragma unroll
    for (int i = 0; i < 4; i++) {
        float inv = rowstat[rg * 4 + i];
        size_t rbase = (size_t)(rg * 4 + i) * S_LEN;
#pragma unroll
        for (int m = 0; m < 16; m++) {
            attnb[rbase + m * 64 + cg] = acc[i][m] * inv;
        }
    }
}

// ---------------------------------------------------------------------------
extern "C" void kernel_launch(void* const* d_in, const int* in_sizes, int n_in,
                              void* d_out, int out_size)
{
    const float* Q    = (const float*)d_in[0];
    const float* Kt   = (const float*)d_in[1];
    const float* V    = (const float*)d_in[2];
    const float* mask = (const float*)d_in[3];

    float* ctx  = (float*)d_out;                                  // [BH,1024,64]
    float* attn = ctx + (size_t)BH * S_LEN * D_DIM;               // [BH,1024,1024]

    void* mkptr = nullptr;
    cudaGetSymbolAddress(&mkptr, g_MK);
    float* MK = (float*)mkptr;

    cudaFuncSetAttribute(scores_softmax_kernel,
                         cudaFuncAttributeMaxDynamicSharedMemorySize,
                         K2_SMEM_BYTES);

    // K1: MK = mask @ K        (mma.sync tf32, 2-limb split)
    gemm_tc_kernel<<<dim3(8, BH), 256>>>(mask, Kt, MK);
    // K2: attn = softmax(scale * Q @ MK^T)   (fp32)
    scores_softmax_kernel<<<dim3(32, BH), 512, K2_SMEM_BYTES>>>(Q, MK, attn);
    // K3: ctx = attn @ V       (mma.sync tf32)
    gemm_tc_kernel<<<dim3(8, BH), 256>>>(attn, V, ctx);
}